// round 16
// baseline (speedup 1.0000x reference)
#include <cuda_runtime.h>
#include <cstdint>

// ---------------- problem constants (fixed-shape problem) ----------------
constexpr int NN    = 10000;  // nodes
constexpr int F1    = 64;     // hidden feat
constexpr int COUT  = 16;     // classes
constexpr int E_MAX = 320000;

// GEMM1 (mma.sync bf16 m16n8k16 hi/lo) tiling
constexpr int BM     = 128;
constexpr int BK     = 16;
constexpr int SPLIT  = 37;        // 79*37=2923 CTAs over 296 slots: 1.9% tail
constexpr int NCH    = NN / BK;   // 625 exact
constexpr int LDK    = 20;        // padded k-stride (floats)
constexpr int STAGES = 4;

// ---------------- device scratch (no allocation; device-code refs only) --
__device__ __align__(16) int   g_cnt[NN];
__device__ __align__(16) int   g_fill[NN];
__device__ __align__(16) int   g_ptr[NN + 1];
__device__ __align__(16) int   g_csrc[E_MAX];
__device__ __align__(16) float g_dinv[NN];
__device__ __align__(16) float g_bufA[(size_t)NN * F1];
__device__ __align__(16) float g_bufB[(size_t)NN * F1];
__device__ __align__(16) float g_part[(size_t)SPLIT * NN * F1];   // ~95 MB
__device__ __align__(16) uint4 g_wbf[(size_t)NCH * 256];

__device__ __forceinline__ int clampN(int v) {
    v = v < 0 ? 0 : v;
    return v < NN ? v : NN - 1;
}

// ---------------- PTX helpers ----------------
__device__ __forceinline__ uint32_t packbf(float hiw, float low) {
    uint32_t r;
    asm("cvt.rn.bf16x2.f32 %0, %1, %2;" : "=r"(r) : "f"(hiw), "f"(low));
    return r;
}
__device__ __forceinline__ void bfsplit2(float e0, float e1, uint32_t& hi, uint32_t& lo) {
    hi = packbf(e1, e0);
    const float h0 = __uint_as_float(hi << 16);
    const float h1 = __uint_as_float(hi & 0xFFFF0000u);
    lo = packbf(e1 - h1, e0 - h0);
}
__device__ __forceinline__ void mma16(float* d, const uint32_t* a, uint32_t b0, uint32_t b1) {
    asm volatile(
        "mma.sync.aligned.m16n8k16.row.col.f32.bf16.bf16.f32 "
        "{%0,%1,%2,%3},{%4,%5,%6,%7},{%8,%9},{%0,%1,%2,%3};"
        : "+f"(d[0]), "+f"(d[1]), "+f"(d[2]), "+f"(d[3])
        : "r"(a[0]), "r"(a[1]), "r"(a[2]), "r"(a[3]), "r"(b0), "r"(b1));
}
__device__ __forceinline__ void cp16(uint32_t dst, const void* src) {
    asm volatile("cp.async.cg.shared.global [%0], [%1], 16;" :: "r"(dst), "l"(src));
}

// ---------------- degree / CSR build ----------------
__global__ void deg_init_kernel() {
    int i = blockIdx.x * blockDim.x + threadIdx.x;
    if (i < NN) { g_cnt[i] = 0; g_fill[i] = 0; }
}
__global__ void deg_count_kernel(const int* __restrict__ ei, int E) {
    int e = blockIdx.x * blockDim.x + threadIdx.x;
    if (e < E) atomicAdd(&g_cnt[clampN(ei[E + e])], 1);
}
// exclusive prefix scan of g_cnt -> g_ptr; ALSO writes g_dinv (fused)
__global__ void csr_scan_kernel() {
    __shared__ int wsum[32];
    __shared__ int woff[32];
    const int tid  = threadIdx.x;
    const int lane = tid & 31;
    const int wid  = tid >> 5;
    constexpr int PER = (NN + 1023) / 1024;  // 10
    const int base = tid * PER;
    int local[PER];
    int tsum = 0;
    #pragma unroll
    for (int i = 0; i < PER; ++i) {
        const int idx = base + i;
        const int v = (idx < NN) ? g_cnt[idx] : 0;
        if (idx < NN) g_dinv[idx] = rsqrtf(1.0f + (float)v);   // fused dinv
        local[i] = tsum;
        tsum += v;
    }
    int inc = tsum;
    #pragma unroll
    for (int o = 1; o < 32; o <<= 1) {
        const int v = __shfl_up_sync(0xFFFFFFFFu, inc, o);
        if (lane >= o) inc += v;
    }
    if (lane == 31) wsum[wid] = inc;
    __syncthreads();
    if (wid == 0) {
        int v = wsum[lane];
        int inc2 = v;
        #pragma unroll
        for (int o = 1; o < 32; o <<= 1) {
            const int u = __shfl_up_sync(0xFFFFFFFFu, inc2, o);
            if (lane >= o) inc2 += u;
        }
        woff[lane] = inc2 - v;
    }
    __syncthreads();
    const int tbase = woff[wid] + (inc - tsum);
    #pragma unroll
    for (int i = 0; i < PER; ++i) {
        const int idx = base + i;
        if (idx < NN) g_ptr[idx] = tbase + local[i];
    }
    if (tid == 1023) g_ptr[NN] = tbase + tsum;
}
__global__ void csr_scatter_kernel(const int* __restrict__ ei, int E) {
    int e = blockIdx.x * blockDim.x + threadIdx.x;
    if (e < E) {
        const int src = clampN(ei[e]);
        const int dst = clampN(ei[E + e]);
        int pos = g_ptr[dst] + atomicAdd(&g_fill[dst], 1);
        pos = pos < E_MAX ? (pos < 0 ? 0 : pos) : E_MAX - 1;
        g_csrc[pos] = src;
    }
}

// ---------------- W1 -> fragment-order packed bf16 hi/lo [verified r11] ---
__global__ void wfrag_kernel(const float* __restrict__ W) {
    int idx = blockIdx.x * blockDim.x + threadIdx.x;
    if (idx >= NCH * 256) return;
    const int lane = idx & 31;
    const int n8   = (idx >> 5) & 7;
    const int c    = idx >> 8;
    const int g = lane >> 2, t = lane & 3;
    const int n  = n8 * 8 + g;
    const int k0 = c * 16 + 2 * t;
    const float w00 = W[(size_t)k0 * 64 + n];
    const float w01 = W[(size_t)(k0 + 1) * 64 + n];
    const float w10 = W[(size_t)(k0 + 8) * 64 + n];
    const float w11 = W[(size_t)(k0 + 9) * 64 + n];
    uint32_t b0h, b0l, b1h, b1l;
    bfsplit2(w00, w01, b0h, b0l);
    bfsplit2(w10, w11, b1h, b1l);
    uint4 v;
    v.x = b0h; v.y = b1h; v.z = b0l; v.w = b1l;
    g_wbf[idx] = v;
}

// ---- GEMM1: bf16 hi/lo, 16x64 warp tiles, split-K, 4-stage pipeline -----
__global__ void __launch_bounds__(256, 2) gemm1_mma_kernel(const float* __restrict__ A) {
    __shared__ __align__(16) float As[STAGES][BM][LDK];
    __shared__ __align__(16) uint4 Bf[STAGES][256];

    const int tid  = threadIdx.x;
    const int lane = tid & 31;
    const int wid  = tid >> 5;
    const int g    = lane >> 2;
    const int t    = lane & 3;
    const int m0   = blockIdx.x * BM;
    const int part = blockIdx.y;

    const int q = NCH / SPLIT, r = NCH % SPLIT;   // 16, 33
    const int cBeg = part * q + (part < r ? part : r);
    const int nCh  = q + (part < r ? 1 : 0);

    const int am0 = tid >> 2,         aj0 = (tid & 3) * 4;
    const int am1 = (tid + 256) >> 2, aj1 = ((tid + 256) & 3) * 4;
    const float* Ap0 = A + (size_t)clampN(m0 + am0) * NN + aj0;
    const float* Ap1 = A + (size_t)clampN(m0 + am1) * NN + aj1;

    const uint32_t aDst0 = (uint32_t)__cvta_generic_to_shared(&As[0][am0][aj0]);
    const uint32_t aDst1 = (uint32_t)__cvta_generic_to_shared(&As[0][am1][aj1]);
    const uint32_t bDst  = (uint32_t)__cvta_generic_to_shared(&Bf[0][0]);
    const uint32_t stageA = (uint32_t)(BM * LDK * 4);
    const uint32_t stageB = 4096u;

    float acc[8][4] = {};

    #pragma unroll
    for (int p = 0; p < STAGES - 1; ++p) {
        if (p < nCh) {
            const size_t kf = (size_t)(cBeg + p) * BK;
            cp16(aDst0 + (uint32_t)p * stageA, Ap0 + kf);
            cp16(aDst1 + (uint32_t)p * stageA, Ap1 + kf);
            cp16(bDst + (uint32_t)p * stageB + (uint32_t)tid * 16,
                 &g_wbf[(size_t)(cBeg + p) * 256 + tid]);
        }
        asm volatile("cp.async.commit_group;");
    }

    for (int i = 0; i < nCh; ++i) {
        const int s   = i & (STAGES - 1);
        const int rem = nCh - 1 - i;
        if (rem >= 2)      asm volatile("cp.async.wait_group 2;");
        else if (rem == 1) asm volatile("cp.async.wait_group 1;");
        else               asm volatile("cp.async.wait_group 0;");
        __syncthreads();

        if (i + STAGES - 1 < nCh) {
            const int ns = (i + STAGES - 1) & (STAGES - 1);
            const size_t kf = (size_t)(cBeg + i + STAGES - 1) * BK;
            cp16(aDst0 + (uint32_t)ns * stageA, Ap0 + kf);
            cp16(aDst1 + (uint32_t)ns * stageA, Ap1 + kf);
            cp16(bDst + (uint32_t)ns * stageB + (uint32_t)tid * 16,
                 &g_wbf[(size_t)(cBeg + i + STAGES - 1) * 256 + tid]);
            asm volatile("cp.async.commit_group;");
        }

        uint4 bv[8];
        #pragma unroll
        for (int n8 = 0; n8 < 8; ++n8)
            bv[n8] = Bf[s][n8 * 32 + lane];

        const int r0 = wid * 16 + g;
        const float2 p0 = *reinterpret_cast<const float2*>(&As[s][r0][2 * t]);
        const float2 p1 = *reinterpret_cast<const float2*>(&As[s][r0 + 8][2 * t]);
        const float2 p2 = *reinterpret_cast<const float2*>(&As[s][r0][2 * t + 8]);
        const float2 p3 = *reinterpret_cast<const float2*>(&As[s][r0 + 8][2 * t + 8]);
        uint32_t ah[4], al[4];
        bfsplit2(p0.x, p0.y, ah[0], al[0]);
        bfsplit2(p1.x, p1.y, ah[1], al[1]);
        bfsplit2(p2.x, p2.y, ah[2], al[2]);
        bfsplit2(p3.x, p3.y, ah[3], al[3]);

        #pragma unroll
        for (int n8 = 0; n8 < 8; ++n8)
            mma16(acc[n8], ah, bv[n8].x, bv[n8].y);   // hi*hi
        #pragma unroll
        for (int n8 = 0; n8 < 8; ++n8)
            mma16(acc[n8], ah, bv[n8].z, bv[n8].w);   // hi*lo
        #pragma unroll
        for (int n8 = 0; n8 < 8; ++n8)
            mma16(acc[n8], al, bv[n8].x, bv[n8].y);   // lo*hi
    }

    float* outp = &g_part[(size_t)part * NN * F1];
    const int r0g = m0 + wid * 16 + g;
    const int r1g = r0g + 8;
    #pragma unroll
    for (int n8 = 0; n8 < 8; ++n8) {
        const int col = n8 * 8 + 2 * t;
        if (r0g < NN) {
            float2 v0 = make_float2(acc[n8][0], acc[n8][1]);
            *reinterpret_cast<float2*>(&outp[(size_t)r0g * F1 + col]) = v0;
        }
        if (r1g < NN) {
            float2 v1 = make_float2(acc[n8][2], acc[n8][3]);
            *reinterpret_cast<float2*>(&outp[(size_t)r1g * F1 + col]) = v1;
        }
    }
}

// reduce split-K partials -> g_bufA
__global__ void reduce_part_kernel() {
    int idx4 = blockIdx.x * blockDim.x + threadIdx.x;
    if (idx4 < NN * F1 / 4) {
        float4 s = make_float4(0.f, 0.f, 0.f, 0.f);
        #pragma unroll 8
        for (int p = 0; p < SPLIT; ++p) {
            const float4 v = *reinterpret_cast<const float4*>(
                &g_part[(size_t)p * NN * F1 + (size_t)idx4 * 4]);
            s.x += v.x; s.y += v.y; s.z += v.z; s.w += v.w;
        }
        *reinterpret_cast<float4*>(&g_bufA[(size_t)idx4 * 4]) = s;
    }
}

// ---- small GEMMs: g_bufB [NN,64] x W [64,C] -> g_bufA --------------------
template <int CIN, int C>
__global__ void gemm_small_kernel(const float* __restrict__ W) {
    __shared__ float w_s[CIN * C];
    for (int i = threadIdx.x; i < CIN * C; i += blockDim.x) w_s[i] = W[i];
    __syncthreads();
    const int total  = NN * C;
    const int stride = gridDim.x * blockDim.x;
    for (int idx = blockIdx.x * blockDim.x + threadIdx.x; idx < total; idx += stride) {
        const int row = idx / C;
        const int col = idx % C;
        const float* rp = &g_bufB[(size_t)row * CIN];
        float acc = 0.0f;
        #pragma unroll
        for (int k = 0; k < CIN; ++k) acc += rp[k] * w_s[k * C + col];
        g_bufA[idx] = acc;
    }
}

// ---- CSR pull aggregation (+fused bias/relu) [verified r14] --------------
template <int C, bool BIAS_RELU>
__global__ void agg_csr_kernel(const float* __restrict__ bias) {
    const int w    = (blockIdx.x * blockDim.x + threadIdx.x) >> 5;
    const int lane = threadIdx.x & 31;
    if (w >= NN) return;
    constexpr int L = C / 2;
    const int dst = w;
    const float dd = g_dinv[dst];
    const int p0 = g_ptr[dst];
    const int p1 = g_ptr[dst + 1];

    float2 acc = make_float2(0.f, 0.f);
    if (lane < L) {
        const float2 v = *reinterpret_cast<const float2*>(&g_bufA[(size_t)dst * C + lane * 2]);
        acc.x = v.x * dd * dd;
        acc.y = v.y * dd * dd;
    }
    int j = p0;
    for (; j + 1 < p1; j += 2) {
        const int s0 = g_csrc[j];
        const int s1 = g_csrc[j + 1];
        const float n0 = g_dinv[s0] * dd;
        const float n1 = g_dinv[s1] * dd;
        if (lane < L) {
            const float2 v0 = *reinterpret_cast<const float2*>(&g_bufA[(size_t)s0 * C + lane * 2]);
            const float2 v1 = *reinterpret_cast<const float2*>(&g_bufA[(size_t)s1 * C + lane * 2]);
            acc.x += v0.x * n0; acc.y += v0.y * n0;
            acc.x += v1.x * n1; acc.y += v1.y * n1;
        }
    }
    if (j < p1) {
        const int s0 = g_csrc[j];
        const float n0 = g_dinv[s0] * dd;
        if (lane < L) {
            const float2 v0 = *reinterpret_cast<const float2*>(&g_bufA[(size_t)s0 * C + lane * 2]);
            acc.x += v0.x * n0; acc.y += v0.y * n0;
        }
    }
    if (lane < L) {
        if (BIAS_RELU) {
            const float2 bb = *reinterpret_cast<const float2*>(&bias[lane * 2]);
            acc.x = fmaxf(acc.x + bb.x, 0.f);
            acc.y = fmaxf(acc.y + bb.y, 0.f);
        }
        *reinterpret_cast<float2*>(&g_bufB[(size_t)dst * C + lane * 2]) = acc;
    }
}

// ---------------- softmax (adds bias b3) ----------------
__global__ void softmax_kernel(const float* __restrict__ b, float* __restrict__ out) {
    int r = blockIdx.x * blockDim.x + threadIdx.x;
    if (r >= NN) return;
    float v[COUT];
    float m = -1e30f;
    #pragma unroll
    for (int j = 0; j < COUT; ++j) {
        v[j] = g_bufB[(size_t)r * COUT + j] + b[j];
        m = fmaxf(m, v[j]);
    }
    float s = 0.0f;
    #pragma unroll
    for (int j = 0; j < COUT; ++j) {
        v[j] = expf(v[j] - m);
        s += v[j];
    }
    const float inv = 1.0f / s;
    #pragma unroll
    for (int j = 0; j < COUT; ++j) out[(size_t)r * COUT + j] = v[j] * inv;
}

// ---------------- launch ----------------
extern "C" void kernel_launch(void* const* d_in, const int* in_sizes, int n_in,
                              void* d_out, int out_size) {
    const float* x  = (const float*)d_in[0];
    const int*   ei = (const int*)d_in[1];   // int32 (JAX x64 disabled)
    const float* W1 = (const float*)d_in[2];
    const float* b1 = (const float*)d_in[3];
    const float* W2 = (const float*)d_in[4];
    const float* b2 = (const float*)d_in[5];
    const float* W3 = (const float*)d_in[6];
    const float* b3 = (const float*)d_in[7];
    float* out = (float*)d_out;

    int E = in_sizes[1] / 2;
    if (E > E_MAX) E = E_MAX;

    const int T = 256;
    const int gN    = (NN + T - 1) / T;
    const int gE    = (E + T - 1) / T;
    const int g64v  = (NN * F1 / 4 + T - 1) / T;
    const int gWarp = (NN * 32 + T - 1) / T;
    const dim3 gG((NN + BM - 1) / BM, SPLIT);   // 79 x 37

    // degree + CSR (dinv fused into scan) + W1 prep
    deg_init_kernel<<<gN, T>>>();
    deg_count_kernel<<<gE, T>>>(ei, E);
    csr_scan_kernel<<<1, 1024>>>();
    csr_scatter_kernel<<<gE, T>>>(ei, E);
    wfrag_kernel<<<(NCH * 256 + T - 1) / T, T>>>(W1);

    // ---- layer 1 ----
    gemm1_mma_kernel<<<gG, 256>>>(x);
    reduce_part_kernel<<<g64v, T>>>();
    agg_csr_kernel<F1, true><<<gWarp, T>>>(b1);

    // ---- layer 2 ----
    gemm_small_kernel<F1, F1><<<1480, T>>>(W2);
    agg_csr_kernel<F1, true><<<gWarp, T>>>(b2);

    // ---- layer 3 ----
    gemm_small_kernel<F1, COUT><<<1480, T>>>(W3);
    agg_csr_kernel<COUT, false><<<gWarp, T>>>(nullptr);
    softmax_kernel<<<gN, T>>>(b3, out);
}

// round 17
// speedup vs baseline: 1.0567x; 1.0567x over previous
#include <cuda_runtime.h>
#include <cstdint>

// ---------------- problem constants (fixed-shape problem) ----------------
constexpr int NN    = 10000;  // nodes
constexpr int F1    = 64;     // hidden feat
constexpr int COUT  = 16;     // classes
constexpr int E_MAX = 320000;

// GEMM1 (mma.sync bf16 m16n8k16 hi/lo) tiling
constexpr int BM     = 128;
constexpr int BK     = 16;
constexpr int SPLIT  = 16;        // best measured (r15); larger splits lose to traffic
constexpr int NCH    = NN / BK;   // 625 exact
constexpr int LDK    = 20;        // padded k-stride (floats)
constexpr int STAGES = 4;

// ---------------- device scratch (no allocation; device-code refs only) --
__device__ __align__(16) int   g_cnt[NN];
__device__ __align__(16) int   g_fill[NN];
__device__ __align__(16) int   g_ptr[NN + 1];
__device__ __align__(16) int   g_csrc[E_MAX];
__device__ __align__(16) float g_dinv[NN];
__device__ __align__(16) float g_bufA[(size_t)NN * F1];
__device__ __align__(16) float g_bufB[(size_t)NN * F1];
__device__ __align__(16) float g_part[(size_t)SPLIT * NN * F1];   // ~41 MB
__device__ __align__(16) uint4 g_wbf[(size_t)NCH * 256];

__device__ __forceinline__ int clampN(int v) {
    v = v < 0 ? 0 : v;
    return v < NN ? v : NN - 1;
}

// ---------------- PTX helpers ----------------
__device__ __forceinline__ uint32_t packbf(float hiw, float low) {
    uint32_t r;
    asm("cvt.rn.bf16x2.f32 %0, %1, %2;" : "=r"(r) : "f"(hiw), "f"(low));
    return r;
}
__device__ __forceinline__ void bfsplit2(float e0, float e1, uint32_t& hi, uint32_t& lo) {
    hi = packbf(e1, e0);
    const float h0 = __uint_as_float(hi << 16);
    const float h1 = __uint_as_float(hi & 0xFFFF0000u);
    lo = packbf(e1 - h1, e0 - h0);
}
__device__ __forceinline__ void mma16(float* d, const uint32_t* a, uint32_t b0, uint32_t b1) {
    asm volatile(
        "mma.sync.aligned.m16n8k16.row.col.f32.bf16.bf16.f32 "
        "{%0,%1,%2,%3},{%4,%5,%6,%7},{%8,%9},{%0,%1,%2,%3};"
        : "+f"(d[0]), "+f"(d[1]), "+f"(d[2]), "+f"(d[3])
        : "r"(a[0]), "r"(a[1]), "r"(a[2]), "r"(a[3]), "r"(b0), "r"(b1));
}
__device__ __forceinline__ void cp16(uint32_t dst, const void* src) {
    asm volatile("cp.async.cg.shared.global [%0], [%1], 16;" :: "r"(dst), "l"(src));
}

// ---------------- degree / CSR build ----------------
__global__ void deg_init_kernel() {
    int i = blockIdx.x * blockDim.x + threadIdx.x;
    if (i < NN) { g_cnt[i] = 0; g_fill[i] = 0; }
}
__global__ void deg_count_kernel(const int* __restrict__ ei, int E) {
    int e = blockIdx.x * blockDim.x + threadIdx.x;
    if (e < E) atomicAdd(&g_cnt[clampN(ei[E + e])], 1);
}
// exclusive prefix scan of g_cnt -> g_ptr; ALSO writes g_dinv (fused)
__global__ void csr_scan_kernel() {
    __shared__ int wsum[32];
    __shared__ int woff[32];
    const int tid  = threadIdx.x;
    const int lane = tid & 31;
    const int wid  = tid >> 5;
    constexpr int PER = (NN + 1023) / 1024;  // 10
    const int base = tid * PER;
    int local[PER];
    int tsum = 0;
    #pragma unroll
    for (int i = 0; i < PER; ++i) {
        const int idx = base + i;
        const int v = (idx < NN) ? g_cnt[idx] : 0;
        if (idx < NN) g_dinv[idx] = rsqrtf(1.0f + (float)v);   // fused dinv
        local[i] = tsum;
        tsum += v;
    }
    int inc = tsum;
    #pragma unroll
    for (int o = 1; o < 32; o <<= 1) {
        const int v = __shfl_up_sync(0xFFFFFFFFu, inc, o);
        if (lane >= o) inc += v;
    }
    if (lane == 31) wsum[wid] = inc;
    __syncthreads();
    if (wid == 0) {
        int v = wsum[lane];
        int inc2 = v;
        #pragma unroll
        for (int o = 1; o < 32; o <<= 1) {
            const int u = __shfl_up_sync(0xFFFFFFFFu, inc2, o);
            if (lane >= o) inc2 += u;
        }
        woff[lane] = inc2 - v;
    }
    __syncthreads();
    const int tbase = woff[wid] + (inc - tsum);
    #pragma unroll
    for (int i = 0; i < PER; ++i) {
        const int idx = base + i;
        if (idx < NN) g_ptr[idx] = tbase + local[i];
    }
    if (tid == 1023) g_ptr[NN] = tbase + tsum;
}
__global__ void csr_scatter_kernel(const int* __restrict__ ei, int E) {
    int e = blockIdx.x * blockDim.x + threadIdx.x;
    if (e < E) {
        const int src = clampN(ei[e]);
        const int dst = clampN(ei[E + e]);
        int pos = g_ptr[dst] + atomicAdd(&g_fill[dst], 1);
        pos = pos < E_MAX ? (pos < 0 ? 0 : pos) : E_MAX - 1;
        g_csrc[pos] = src;
    }
}

// ---------------- W1 -> fragment-order packed bf16 hi/lo [verified r11] ---
__global__ void wfrag_kernel(const float* __restrict__ W) {
    int idx = blockIdx.x * blockDim.x + threadIdx.x;
    if (idx >= NCH * 256) return;
    const int lane = idx & 31;
    const int n8   = (idx >> 5) & 7;
    const int c    = idx >> 8;
    const int g = lane >> 2, t = lane & 3;
    const int n  = n8 * 8 + g;
    const int k0 = c * 16 + 2 * t;
    const float w00 = W[(size_t)k0 * 64 + n];
    const float w01 = W[(size_t)(k0 + 1) * 64 + n];
    const float w10 = W[(size_t)(k0 + 8) * 64 + n];
    const float w11 = W[(size_t)(k0 + 9) * 64 + n];
    uint32_t b0h, b0l, b1h, b1l;
    bfsplit2(w00, w01, b0h, b0l);
    bfsplit2(w10, w11, b1h, b1l);
    uint4 v;
    v.x = b0h; v.y = b1h; v.z = b0l; v.w = b1l;
    g_wbf[idx] = v;
}

// ---- GEMM1: bf16 hi/lo, 16x64 warp tiles, split-K, 4-stage pipeline -----
__global__ void __launch_bounds__(256, 2) gemm1_mma_kernel(const float* __restrict__ A) {
    __shared__ __align__(16) float As[STAGES][BM][LDK];
    __shared__ __align__(16) uint4 Bf[STAGES][256];

    const int tid  = threadIdx.x;
    const int lane = tid & 31;
    const int wid  = tid >> 5;
    const int g    = lane >> 2;
    const int t    = lane & 3;
    const int m0   = blockIdx.x * BM;
    const int part = blockIdx.y;

    const int q = NCH / SPLIT, r = NCH % SPLIT;   // 39, 1
    const int cBeg = part * q + (part < r ? part : r);
    const int nCh  = q + (part < r ? 1 : 0);

    const int am0 = tid >> 2,         aj0 = (tid & 3) * 4;
    const int am1 = (tid + 256) >> 2, aj1 = ((tid + 256) & 3) * 4;
    const float* Ap0 = A + (size_t)clampN(m0 + am0) * NN + aj0;
    const float* Ap1 = A + (size_t)clampN(m0 + am1) * NN + aj1;

    const uint32_t aDst0 = (uint32_t)__cvta_generic_to_shared(&As[0][am0][aj0]);
    const uint32_t aDst1 = (uint32_t)__cvta_generic_to_shared(&As[0][am1][aj1]);
    const uint32_t bDst  = (uint32_t)__cvta_generic_to_shared(&Bf[0][0]);
    const uint32_t stageA = (uint32_t)(BM * LDK * 4);
    const uint32_t stageB = 4096u;

    float acc[8][4] = {};

    #pragma unroll
    for (int p = 0; p < STAGES - 1; ++p) {
        if (p < nCh) {
            const size_t kf = (size_t)(cBeg + p) * BK;
            cp16(aDst0 + (uint32_t)p * stageA, Ap0 + kf);
            cp16(aDst1 + (uint32_t)p * stageA, Ap1 + kf);
            cp16(bDst + (uint32_t)p * stageB + (uint32_t)tid * 16,
                 &g_wbf[(size_t)(cBeg + p) * 256 + tid]);
        }
        asm volatile("cp.async.commit_group;");
    }

    for (int i = 0; i < nCh; ++i) {
        const int s   = i & (STAGES - 1);
        const int rem = nCh - 1 - i;
        if (rem >= 2)      asm volatile("cp.async.wait_group 2;");
        else if (rem == 1) asm volatile("cp.async.wait_group 1;");
        else               asm volatile("cp.async.wait_group 0;");
        __syncthreads();

        if (i + STAGES - 1 < nCh) {
            const int ns = (i + STAGES - 1) & (STAGES - 1);
            const size_t kf = (size_t)(cBeg + i + STAGES - 1) * BK;
            cp16(aDst0 + (uint32_t)ns * stageA, Ap0 + kf);
            cp16(aDst1 + (uint32_t)ns * stageA, Ap1 + kf);
            cp16(bDst + (uint32_t)ns * stageB + (uint32_t)tid * 16,
                 &g_wbf[(size_t)(cBeg + i + STAGES - 1) * 256 + tid]);
            asm volatile("cp.async.commit_group;");
        }

        uint4 bv[8];
        #pragma unroll
        for (int n8 = 0; n8 < 8; ++n8)
            bv[n8] = Bf[s][n8 * 32 + lane];

        const int r0 = wid * 16 + g;
        const float2 p0 = *reinterpret_cast<const float2*>(&As[s][r0][2 * t]);
        const float2 p1 = *reinterpret_cast<const float2*>(&As[s][r0 + 8][2 * t]);
        const float2 p2 = *reinterpret_cast<const float2*>(&As[s][r0][2 * t + 8]);
        const float2 p3 = *reinterpret_cast<const float2*>(&As[s][r0 + 8][2 * t + 8]);
        uint32_t ah[4], al[4];
        bfsplit2(p0.x, p0.y, ah[0], al[0]);
        bfsplit2(p1.x, p1.y, ah[1], al[1]);
        bfsplit2(p2.x, p2.y, ah[2], al[2]);
        bfsplit2(p3.x, p3.y, ah[3], al[3]);

        #pragma unroll
        for (int n8 = 0; n8 < 8; ++n8)
            mma16(acc[n8], ah, bv[n8].x, bv[n8].y);   // hi*hi
        #pragma unroll
        for (int n8 = 0; n8 < 8; ++n8)
            mma16(acc[n8], ah, bv[n8].z, bv[n8].w);   // hi*lo
        #pragma unroll
        for (int n8 = 0; n8 < 8; ++n8)
            mma16(acc[n8], al, bv[n8].x, bv[n8].y);   // lo*hi
    }

    float* outp = &g_part[(size_t)part * NN * F1];
    const int r0g = m0 + wid * 16 + g;
    const int r1g = r0g + 8;
    #pragma unroll
    for (int n8 = 0; n8 < 8; ++n8) {
        const int col = n8 * 8 + 2 * t;
        if (r0g < NN) {
            float2 v0 = make_float2(acc[n8][0], acc[n8][1]);
            *reinterpret_cast<float2*>(&outp[(size_t)r0g * F1 + col]) = v0;
        }
        if (r1g < NN) {
            float2 v1 = make_float2(acc[n8][2], acc[n8][3]);
            *reinterpret_cast<float2*>(&outp[(size_t)r1g * F1 + col]) = v1;
        }
    }
}

// reduce split-K partials -> g_bufA
__global__ void reduce_part_kernel() {
    int idx4 = blockIdx.x * blockDim.x + threadIdx.x;
    if (idx4 < NN * F1 / 4) {
        float4 s = make_float4(0.f, 0.f, 0.f, 0.f);
        #pragma unroll
        for (int p = 0; p < SPLIT; ++p) {
            const float4 v = *reinterpret_cast<const float4*>(
                &g_part[(size_t)p * NN * F1 + (size_t)idx4 * 4]);
            s.x += v.x; s.y += v.y; s.z += v.z; s.w += v.w;
        }
        *reinterpret_cast<float4*>(&g_bufA[(size_t)idx4 * 4]) = s;
    }
}

// ---- small GEMMs: g_bufB [NN,64] x W [64,C] -> g_bufA --------------------
template <int CIN, int C>
__global__ void gemm_small_kernel(const float* __restrict__ W) {
    __shared__ float w_s[CIN * C];
    for (int i = threadIdx.x; i < CIN * C; i += blockDim.x) w_s[i] = W[i];
    __syncthreads();
    const int total  = NN * C;
    const int stride = gridDim.x * blockDim.x;
    for (int idx = blockIdx.x * blockDim.x + threadIdx.x; idx < total; idx += stride) {
        const int row = idx / C;
        const int col = idx % C;
        const float* rp = &g_bufB[(size_t)row * CIN];
        float acc = 0.0f;
        #pragma unroll
        for (int k = 0; k < CIN; ++k) acc += rp[k] * w_s[k * C + col];
        g_bufA[idx] = acc;
    }
}

// ---- CSR pull aggregation (+fused bias/relu), 4-way MLP unroll -----------
// sequential adds in j order -> numerics identical to 2-way version
template <int C, bool BIAS_RELU>
__global__ void agg_csr_kernel(const float* __restrict__ bias) {
    const int w    = (blockIdx.x * blockDim.x + threadIdx.x) >> 5;
    const int lane = threadIdx.x & 31;
    if (w >= NN) return;
    constexpr int L = C / 2;
    const int dst = w;
    const float dd = g_dinv[dst];
    const int p0 = g_ptr[dst];
    const int p1 = g_ptr[dst + 1];

    float2 acc = make_float2(0.f, 0.f);
    if (lane < L) {
        const float2 v = *reinterpret_cast<const float2*>(&g_bufA[(size_t)dst * C + lane * 2]);
        acc.x = v.x * dd * dd;
        acc.y = v.y * dd * dd;
    }
    int j = p0;
    for (; j + 3 < p1; j += 4) {
        const int s0 = g_csrc[j];
        const int s1 = g_csrc[j + 1];
        const int s2 = g_csrc[j + 2];
        const int s3 = g_csrc[j + 3];
        const float n0 = g_dinv[s0] * dd;
        const float n1 = g_dinv[s1] * dd;
        const float n2 = g_dinv[s2] * dd;
        const float n3 = g_dinv[s3] * dd;
        if (lane < L) {
            const float2 v0 = *reinterpret_cast<const float2*>(&g_bufA[(size_t)s0 * C + lane * 2]);
            const float2 v1 = *reinterpret_cast<const float2*>(&g_bufA[(size_t)s1 * C + lane * 2]);
            const float2 v2 = *reinterpret_cast<const float2*>(&g_bufA[(size_t)s2 * C + lane * 2]);
            const float2 v3 = *reinterpret_cast<const float2*>(&g_bufA[(size_t)s3 * C + lane * 2]);
            acc.x += v0.x * n0; acc.y += v0.y * n0;
            acc.x += v1.x * n1; acc.y += v1.y * n1;
            acc.x += v2.x * n2; acc.y += v2.y * n2;
            acc.x += v3.x * n3; acc.y += v3.y * n3;
        }
    }
    for (; j < p1; ++j) {
        const int s0 = g_csrc[j];
        const float n0 = g_dinv[s0] * dd;
        if (lane < L) {
            const float2 v0 = *reinterpret_cast<const float2*>(&g_bufA[(size_t)s0 * C + lane * 2]);
            acc.x += v0.x * n0; acc.y += v0.y * n0;
        }
    }
    if (lane < L) {
        if (BIAS_RELU) {
            const float2 bb = *reinterpret_cast<const float2*>(&bias[lane * 2]);
            acc.x = fmaxf(acc.x + bb.x, 0.f);
            acc.y = fmaxf(acc.y + bb.y, 0.f);
        }
        *reinterpret_cast<float2*>(&g_bufB[(size_t)dst * C + lane * 2]) = acc;
    }
}

// ---------------- softmax (adds bias b3) ----------------
__global__ void softmax_kernel(const float* __restrict__ b, float* __restrict__ out) {
    int r = blockIdx.x * blockDim.x + threadIdx.x;
    if (r >= NN) return;
    float v[COUT];
    float m = -1e30f;
    #pragma unroll
    for (int j = 0; j < COUT; ++j) {
        v[j] = g_bufB[(size_t)r * COUT + j] + b[j];
        m = fmaxf(m, v[j]);
    }
    float s = 0.0f;
    #pragma unroll
    for (int j = 0; j < COUT; ++j) {
        v[j] = expf(v[j] - m);
        s += v[j];
    }
    const float inv = 1.0f / s;
    #pragma unroll
    for (int j = 0; j < COUT; ++j) out[(size_t)r * COUT + j] = v[j] * inv;
}

// ---------------- launch ----------------
extern "C" void kernel_launch(void* const* d_in, const int* in_sizes, int n_in,
                              void* d_out, int out_size) {
    const float* x  = (const float*)d_in[0];
    const int*   ei = (const int*)d_in[1];   // int32 (JAX x64 disabled)
    const float* W1 = (const float*)d_in[2];
    const float* b1 = (const float*)d_in[3];
    const float* W2 = (const float*)d_in[4];
    const float* b2 = (const float*)d_in[5];
    const float* W3 = (const float*)d_in[6];
    const float* b3 = (const float*)d_in[7];
    float* out = (float*)d_out;

    int E = in_sizes[1] / 2;
    if (E > E_MAX) E = E_MAX;

    const int T = 256;
    const int gN    = (NN + T - 1) / T;
    const int gE    = (E + T - 1) / T;
    const int g64v  = (NN * F1 / 4 + T - 1) / T;
    const int gWarp = (NN * 32 + T - 1) / T;
    const dim3 gG((NN + BM - 1) / BM, SPLIT);   // 79 x 16

    // degree + CSR (dinv fused into scan) + W1 prep
    deg_init_kernel<<<gN, T>>>();
    deg_count_kernel<<<gE, T>>>(ei, E);
    csr_scan_kernel<<<1, 1024>>>();
    csr_scatter_kernel<<<gE, T>>>(ei, E);
    wfrag_kernel<<<(NCH * 256 + T - 1) / T, T>>>(W1);

    // ---- layer 1 ----
    gemm1_mma_kernel<<<gG, 256>>>(x);
    reduce_part_kernel<<<g64v, T>>>();
    agg_csr_kernel<F1, true><<<gWarp, T>>>(b1);

    // ---- layer 2 ----  (one-wave grid: 2368 = 16 CTAs/SM)
    gemm_small_kernel<F1, F1><<<2368, T>>>(W2);
    agg_csr_kernel<F1, true><<<gWarp, T>>>(b2);

    // ---- layer 3 ----
    gemm_small_kernel<F1, COUT><<<2368, T>>>(W3);
    agg_csr_kernel<COUT, false><<<gWarp, T>>>(nullptr);
    softmax_kernel<<<gN, T>>>(b3, out);
}